// round 8
// baseline (speedup 1.0000x reference)
#include <cuda_runtime.h>
#include <cuda_bf16.h>

#define D          128
#define B_MAX      8192
#define CROWS      96           // rows per buffer; 2 * 48 KB = 96 KB dyn -> 2 CTA/SM
#define TPB        256
#define NPROD      4            // producer warps
#define NCONS      4            // consumer warps
#define GS         32           // segments per GEMM block

__device__ float g_pooled[B_MAX * D];
__device__ int   g_seg_start[B_MAX + 1];

// ---------------------------------------------------------------------------
// Kernel 1: segment boundaries via transition scan (batch is sorted), int4.
// ---------------------------------------------------------------------------
__global__ void seg_scan_kernel(const int* __restrict__ batch, int N, int B) {
    int i4 = blockIdx.x * blockDim.x + threadIdx.x;
    int base = i4 * 4;
    if (base >= N) return;

    int vals[4];
    if (base + 3 < N) {
        int4 v = ((const int4*)batch)[i4];
        vals[0] = v.x; vals[1] = v.y; vals[2] = v.z; vals[3] = v.w;
    } else {
        #pragma unroll
        for (int u = 0; u < 4; u++)
            vals[u] = (base + u < N) ? batch[base + u] : 0;
    }

    int prev = (base == 0) ? -1 : batch[base - 1];
    #pragma unroll
    for (int u = 0; u < 4; u++) {
        int idx = base + u;
        if (idx < N) {
            int cur = vals[u];
            for (int b = prev + 1; b <= cur; b++) g_seg_start[b] = idx;
            if (idx == N - 1)
                for (int b = cur + 1; b <= B; b++) g_seg_start[b] = N;
            prev = cur;
        }
    }
}

// ---------------------------------------------------------------------------
// Kernel 2: persistent warp-specialized pool. 2 CTAs/SM.
//   warps 0-3 (producers): stream segment s+G into double buffer + sum.
//   warps 4-7 (consumers): pass B of segment s from buffer (+L2-hit tail).
// Handoff via __syncthreads at segment boundaries.
// ---------------------------------------------------------------------------
__global__ __launch_bounds__(TPB, 2)
void pool_kernel(const float* __restrict__ x, int B) {
    extern __shared__ float4 buf[];            // [2][CROWS*32]
    __shared__ float4 redS[NPROD][32];
    __shared__ float4 redP[NCONS][32];
    __shared__ float4 coarse_s[2][32];

    const int tid  = threadIdx.x;
    const int wid  = tid >> 5;
    const int lane = tid & 31;
    const int G    = gridDim.x;
    const float4* __restrict__ x4 = (const float4*)x;

    const int s0 = blockIdx.x;
    if (s0 >= B) return;

    const bool producer = (wid < NPROD);

    // ---- Prologue: producers load segment s0 into buf[0] ----
    {
        const int st = g_seg_start[s0];
        const int en = g_seg_start[s0 + 1];
        const int ce = (st + CROWS < en) ? st + CROWS : en;
        if (producer) {
            float4 acc = make_float4(0.f, 0.f, 0.f, 0.f);
            const int U = 12;
            int r = st + wid;
            while (r + (U - 1) * NPROD < en) {
                float4 v[U];
                #pragma unroll
                for (int u = 0; u < U; u++)
                    v[u] = x4[(size_t)(r + u * NPROD) * 32 + lane];
                #pragma unroll
                for (int u = 0; u < U; u++) {
                    int cr = r + u * NPROD - st;
                    if (cr < CROWS) buf[cr * 32 + lane] = v[u];
                    acc.x += v[u].x; acc.y += v[u].y; acc.z += v[u].z; acc.w += v[u].w;
                }
                r += U * NPROD;
            }
            for (; r < en; r += NPROD) {
                float4 v = x4[(size_t)r * 32 + lane];
                int cr = r - st;
                if (cr < ce - st && cr < CROWS) buf[cr * 32 + lane] = v;
                acc.x += v.x; acc.y += v.y; acc.z += v.z; acc.w += v.w;
            }
            redS[wid][lane] = acc;
        }
        __syncthreads();
        if (wid == 0) {
            int n = en - st;
            float inv = 1.0f / (float)(n > 0 ? n : 1);
            float4 s = redS[0][lane];
            #pragma unroll
            for (int w = 1; w < NPROD; w++) {
                float4 t = redS[w][lane];
                s.x += t.x; s.y += t.y; s.z += t.z; s.w += t.w;
            }
            s.x *= inv; s.y *= inv; s.z *= inv; s.w *= inv;
            coarse_s[0][lane] = s;
        }
        __syncthreads();
    }

    int pb = 0;
    for (int s = s0; s < B; s += G) {
        const int cstart = g_seg_start[s];
        const int cend   = g_seg_start[s + 1];
        const int ccend  = (cstart + CROWS < cend) ? cstart + CROWS : cend;
        const int cn     = cend - cstart;
        const float inv_cn = 1.0f / (float)(cn > 0 ? cn : 1);
        const int snext  = s + G;

        if (producer) {
            // ---- produce segment snext into buf[pb^1] ----
            if (snext < B) {
                const int nstart = g_seg_start[snext];
                const int nend   = g_seg_start[snext + 1];
                float4* bufn = buf + (pb ^ 1) * (CROWS * 32);
                float4 acc = make_float4(0.f, 0.f, 0.f, 0.f);
                const int U = 12;
                int r = nstart + wid;
                while (r + (U - 1) * NPROD < nend) {
                    float4 v[U];
                    #pragma unroll
                    for (int u = 0; u < U; u++)
                        v[u] = x4[(size_t)(r + u * NPROD) * 32 + lane];
                    #pragma unroll
                    for (int u = 0; u < U; u++) {
                        int cr = r + u * NPROD - nstart;
                        if (cr < CROWS) bufn[cr * 32 + lane] = v[u];
                        acc.x += v[u].x; acc.y += v[u].y;
                        acc.z += v[u].z; acc.w += v[u].w;
                    }
                    r += U * NPROD;
                }
                for (; r < nend; r += NPROD) {
                    float4 v = x4[(size_t)r * 32 + lane];
                    int cr = r - nstart;
                    if (cr < CROWS) bufn[cr * 32 + lane] = v;
                    acc.x += v.x; acc.y += v.y; acc.z += v.z; acc.w += v.w;
                }
                redS[wid][lane] = acc;
            }
        } else {
            // ---- consume segment s: att + weighted accumulate ----
            const int cw = wid - NPROD;
            const float4 c = coarse_s[pb][lane];
            const float4* bufc = buf + pb * (CROWS * 32);
            float4 pacc = make_float4(0.f, 0.f, 0.f, 0.f);

            // (1) tail rows from global (L2 hits: streamed one segment ago)
            {
                const int U = 6;
                int r = ccend + cw;
                while (r + (U - 1) * NCONS < cend) {
                    float4 v[U];
                    float  p[U];
                    #pragma unroll
                    for (int u = 0; u < U; u++)
                        v[u] = x4[(size_t)(r + u * NCONS) * 32 + lane];
                    #pragma unroll
                    for (int u = 0; u < U; u++)
                        p[u] = v[u].x * c.x + v[u].y * c.y + v[u].z * c.z + v[u].w * c.w;
                    #pragma unroll
                    for (int o = 16; o; o >>= 1) {
                        #pragma unroll
                        for (int u = 0; u < U; u++)
                            p[u] += __shfl_xor_sync(0xffffffffu, p[u], o);
                    }
                    #pragma unroll
                    for (int u = 0; u < U; u++) {
                        pacc.x += p[u] * v[u].x; pacc.y += p[u] * v[u].y;
                        pacc.z += p[u] * v[u].z; pacc.w += p[u] * v[u].w;
                    }
                    r += U * NCONS;
                }
                for (; r < cend; r += NCONS) {
                    float4 v = x4[(size_t)r * 32 + lane];
                    float p = v.x * c.x + v.y * c.y + v.z * c.z + v.w * c.w;
                    #pragma unroll
                    for (int o = 16; o; o >>= 1)
                        p += __shfl_xor_sync(0xffffffffu, p, o);
                    pacc.x += p * v.x; pacc.y += p * v.y;
                    pacc.z += p * v.z; pacc.w += p * v.w;
                }
            }
            // (2) cached rows from SMEM
            {
                const int U = 4;
                int r = cstart + cw;
                while (r + (U - 1) * NCONS < ccend) {
                    float4 v[U];
                    float  p[U];
                    #pragma unroll
                    for (int u = 0; u < U; u++)
                        v[u] = bufc[(r + u * NCONS - cstart) * 32 + lane];
                    #pragma unroll
                    for (int u = 0; u < U; u++)
                        p[u] = v[u].x * c.x + v[u].y * c.y + v[u].z * c.z + v[u].w * c.w;
                    #pragma unroll
                    for (int o = 16; o; o >>= 1) {
                        #pragma unroll
                        for (int u = 0; u < U; u++)
                            p[u] += __shfl_xor_sync(0xffffffffu, p[u], o);
                    }
                    #pragma unroll
                    for (int u = 0; u < U; u++) {
                        pacc.x += p[u] * v[u].x; pacc.y += p[u] * v[u].y;
                        pacc.z += p[u] * v[u].z; pacc.w += p[u] * v[u].w;
                    }
                    r += U * NCONS;
                }
                for (; r < ccend; r += NCONS) {
                    float4 v = bufc[(r - cstart) * 32 + lane];
                    float p = v.x * c.x + v.y * c.y + v.z * c.z + v.w * c.w;
                    #pragma unroll
                    for (int o = 16; o; o >>= 1)
                        p += __shfl_xor_sync(0xffffffffu, p, o);
                    pacc.x += p * v.x; pacc.y += p * v.y;
                    pacc.z += p * v.z; pacc.w += p * v.w;
                }
            }
            redP[cw][lane] = pacc;
        }

        __syncthreads();

        if (wid == 0 && snext < B) {
            int nn = g_seg_start[snext + 1] - g_seg_start[snext];
            float inv = 1.0f / (float)(nn > 0 ? nn : 1);
            float4 sm = redS[0][lane];
            #pragma unroll
            for (int w = 1; w < NPROD; w++) {
                float4 t = redS[w][lane];
                sm.x += t.x; sm.y += t.y; sm.z += t.z; sm.w += t.w;
            }
            sm.x *= inv; sm.y *= inv; sm.z *= inv; sm.w *= inv;
            coarse_s[pb ^ 1][lane] = sm;
        }
        if (wid == NPROD) {
            float4 sm = redP[0][lane];
            #pragma unroll
            for (int w = 1; w < NCONS; w++) {
                float4 t = redP[w][lane];
                sm.x += t.x; sm.y += t.y; sm.z += t.z; sm.w += t.w;
            }
            sm.x *= inv_cn; sm.y *= inv_cn; sm.z *= inv_cn; sm.w *= inv_cn;
            ((float4*)g_pooled)[(size_t)s * 32 + lane] = sm;
        }
        __syncthreads();
        pb ^= 1;
    }
}

// ---------------------------------------------------------------------------
// Kernel 3: out = pooled @ W^T + b    ([B,128] x [128,128])
// ---------------------------------------------------------------------------
__global__ __launch_bounds__(256)
void gemm_kernel(const float* __restrict__ W, const float* __restrict__ bias,
                 float* __restrict__ out, int B) {
    extern __shared__ float sm[];
    float* Wt = sm;                 // [128][132]
    float* ps = sm + 128 * 132;     // [GS][128]

    const int t  = threadIdx.x;
    const int s0 = blockIdx.x * GS;

    for (int idx = t; idx < D * D; idx += 256) {
        int o = idx >> 7, k = idx & 127;
        Wt[k * 132 + o] = W[idx];
    }
    {
        float4* ps4 = (float4*)ps;
        const float4* gp4 = (const float4*)(g_pooled + (size_t)s0 * D);
        int nvec = GS * D / 4;
        for (int idx = t; idx < nvec; idx += 256) {
            int row = s0 + (idx >> 5);
            ps4[idx] = (row < B) ? gp4[idx] : make_float4(0.f, 0.f, 0.f, 0.f);
        }
    }
    __syncthreads();

    const int o4 = (t & 31) * 4;
    const int sb = (t >> 5) * 4;

    float acc[4][4];
    #pragma unroll
    for (int j = 0; j < 4; j++)
        #pragma unroll
        for (int i = 0; i < 4; i++) acc[j][i] = 0.f;

    #pragma unroll 4
    for (int k = 0; k < D; k++) {
        float4 w4 = *(const float4*)&Wt[k * 132 + o4];
        #pragma unroll
        for (int j = 0; j < 4; j++) {
            float pv = ps[(sb + j) * D + k];
            acc[j][0] += pv * w4.x;
            acc[j][1] += pv * w4.y;
            acc[j][2] += pv * w4.z;
            acc[j][3] += pv * w4.w;
        }
    }

    float4 bb = *(const float4*)&bias[o4];
    #pragma unroll
    for (int j = 0; j < 4; j++) {
        int s = s0 + sb + j;
        if (s < B) {
            float4 r = make_float4(acc[j][0] + bb.x, acc[j][1] + bb.y,
                                   acc[j][2] + bb.z, acc[j][3] + bb.w);
            *(float4*)&out[(size_t)s * D + o4] = r;
        }
    }
}

// ---------------------------------------------------------------------------
extern "C" void kernel_launch(void* const* d_in, const int* in_sizes, int n_in,
                              void* d_out, int out_size) {
    const float* x     = (const float*)d_in[0];
    const int*   batch = (const int*)d_in[1];
    const float* W     = (const float*)d_in[2];
    const float* bias  = (const float*)d_in[3];
    (void)n_in;

    const int N = in_sizes[1];
    const int B = out_size / D;

    int nsm = 148;
    cudaDeviceGetAttribute(&nsm, cudaDevAttrMultiProcessorCount, 0);

    const size_t pool_smem = (size_t)2 * CROWS * 32 * sizeof(float4);   // 96 KB
    const size_t gemm_smem = (size_t)(128 * 132 + GS * D) * sizeof(float);

    cudaFuncSetAttribute(pool_kernel, cudaFuncAttributeMaxDynamicSharedMemorySize,
                         (int)pool_smem);
    cudaFuncSetAttribute(gemm_kernel, cudaFuncAttributeMaxDynamicSharedMemorySize,
                         (int)gemm_smem);

    int nvec4 = (N + 3) / 4;
    seg_scan_kernel<<<(nvec4 + 255) / 256, 256>>>(batch, N, B);
    int grid = (2 * nsm < B) ? 2 * nsm : B;
    pool_kernel<<<grid, TPB, pool_smem>>>(x, B);
    gemm_kernel<<<(B + GS - 1) / GS, 256, gemm_smem>>>(W, bias, (float*)d_out, B);
}

// round 9
// speedup vs baseline: 1.2216x; 1.2216x over previous
#include <cuda_runtime.h>
#include <cuda_bf16.h>

#define D          128
#define B_MAX      8192
#define CACHE_ROWS 64           // 64 rows * 512B = 32 KB dynamic smem -> 5 CTA/SM
#define TPB        256
#define NWARP      (TPB / 32)
#define GS         32           // segments per GEMM block

// Scratch (no allocations allowed): pooled means + segment boundaries
__device__ float g_pooled[B_MAX * D];
__device__ int   g_seg_start[B_MAX + 1];

// ---------------------------------------------------------------------------
// Kernel 1: segment boundaries via transition scan (batch is sorted), int4.
// ---------------------------------------------------------------------------
__global__ void seg_scan_kernel(const int* __restrict__ batch, int N, int B) {
    int i4 = blockIdx.x * blockDim.x + threadIdx.x;
    int base = i4 * 4;
    if (base >= N) return;

    int vals[4];
    if (base + 3 < N) {
        int4 v = ((const int4*)batch)[i4];
        vals[0] = v.x; vals[1] = v.y; vals[2] = v.z; vals[3] = v.w;
    } else {
        #pragma unroll
        for (int u = 0; u < 4; u++)
            vals[u] = (base + u < N) ? batch[base + u] : 0;
    }

    int prev = (base == 0) ? -1 : batch[base - 1];
    #pragma unroll
    for (int u = 0; u < 4; u++) {
        int idx = base + u;
        if (idx < N) {
            int cur = vals[u];
            for (int b = prev + 1; b <= cur; b++) g_seg_start[b] = idx;
            if (idx == N - 1)
                for (int b = cur + 1; b <= B; b++) g_seg_start[b] = N;
            prev = cur;
        }
    }
}

// ---------------------------------------------------------------------------
// Kernel 2: one CTA per segment, 5 CTAs/SM (phase mixing keeps DRAM+LTS busy).
//  Pass A: stream rows (6-deep staging), cache first CACHE_ROWS in SMEM,
//          accumulate segment sum -> coarse mean.
//  Pass B: tail (uncached, recent L2 hit) rows first, then cached rows.
// ---------------------------------------------------------------------------
__global__ __launch_bounds__(TPB, 5)
void pool_kernel(const float* __restrict__ x) {
    extern __shared__ float4 cache[];              // [CACHE_ROWS][32]
    __shared__ float4 red[NWARP][32];
    __shared__ float4 coarse_s[32];

    const int seg   = blockIdx.x;
    const int start = g_seg_start[seg];
    const int end   = g_seg_start[seg + 1];
    const int n     = end - start;
    const float inv_n = 1.0f / (float)(n > 0 ? n : 1);
    const int cend  = (start + CACHE_ROWS < end) ? (start + CACHE_ROWS) : end;

    const int tid  = threadIdx.x;
    const int wid  = tid >> 5;
    const int lane = tid & 31;
    const float4* __restrict__ x4 = (const float4*)x;

    // ---- Pass A: segment sum + SMEM cache, 6-deep load staging ----
    float4 acc = make_float4(0.f, 0.f, 0.f, 0.f);
    {
        const int U = 6;
        int r = start + wid;
        while (r + (U - 1) * NWARP < end) {
            float4 v[U];
            #pragma unroll
            for (int u = 0; u < U; u++)
                v[u] = x4[(size_t)(r + u * NWARP) * 32 + lane];
            #pragma unroll
            for (int u = 0; u < U; u++) {
                int cr = r + u * NWARP - start;
                if (cr < CACHE_ROWS) cache[cr * 32 + lane] = v[u];
                acc.x += v[u].x; acc.y += v[u].y; acc.z += v[u].z; acc.w += v[u].w;
            }
            r += U * NWARP;
        }
        for (; r < end; r += NWARP) {
            float4 v = x4[(size_t)r * 32 + lane];
            int cr = r - start;
            if (cr < CACHE_ROWS) cache[cr * 32 + lane] = v;
            acc.x += v.x; acc.y += v.y; acc.z += v.z; acc.w += v.w;
        }
    }
    red[wid][lane] = acc;
    __syncthreads();

    if (wid == 0) {
        float4 s = red[0][lane];
        #pragma unroll
        for (int w = 1; w < NWARP; w++) {
            float4 t = red[w][lane];
            s.x += t.x; s.y += t.y; s.z += t.z; s.w += t.w;
        }
        s.x *= inv_n; s.y *= inv_n; s.z *= inv_n; s.w *= inv_n;
        coarse_s[lane] = s;
    }
    __syncthreads();

    const float4 c = coarse_s[lane];

    // ---- Pass B ----
    float4 pacc = make_float4(0.f, 0.f, 0.f, 0.f);

    // (1) uncached tail rows: loads land as L2 hits (lines touched in pass A)
    {
        const int U = 6;
        int r = cend + wid;
        while (r + (U - 1) * NWARP < end) {
            float4 v[U];
            float  p[U];
            #pragma unroll
            for (int u = 0; u < U; u++)
                v[u] = x4[(size_t)(r + u * NWARP) * 32 + lane];
            #pragma unroll
            for (int u = 0; u < U; u++)
                p[u] = v[u].x * c.x + v[u].y * c.y + v[u].z * c.z + v[u].w * c.w;
            #pragma unroll
            for (int o = 16; o; o >>= 1) {
                #pragma unroll
                for (int u = 0; u < U; u++)
                    p[u] += __shfl_xor_sync(0xffffffffu, p[u], o);
            }
            #pragma unroll
            for (int u = 0; u < U; u++) {
                pacc.x += p[u] * v[u].x; pacc.y += p[u] * v[u].y;
                pacc.z += p[u] * v[u].z; pacc.w += p[u] * v[u].w;
            }
            r += U * NWARP;
        }
        for (; r < end; r += NWARP) {
            float4 v = x4[(size_t)r * 32 + lane];
            float p = v.x * c.x + v.y * c.y + v.z * c.z + v.w * c.w;
            #pragma unroll
            for (int o = 16; o; o >>= 1)
                p += __shfl_xor_sync(0xffffffffu, p, o);
            pacc.x += p * v.x; pacc.y += p * v.y; pacc.z += p * v.z; pacc.w += p * v.w;
        }
    }

    // (2) cached rows from SMEM
    {
        const int U = 4;
        int r = start + wid;
        while (r + (U - 1) * NWARP < cend) {
            float4 v[U];
            float  p[U];
            #pragma unroll
            for (int u = 0; u < U; u++)
                v[u] = cache[(r + u * NWARP - start) * 32 + lane];
            #pragma unroll
            for (int u = 0; u < U; u++)
                p[u] = v[u].x * c.x + v[u].y * c.y + v[u].z * c.z + v[u].w * c.w;
            #pragma unroll
            for (int o = 16; o; o >>= 1) {
                #pragma unroll
                for (int u = 0; u < U; u++)
                    p[u] += __shfl_xor_sync(0xffffffffu, p[u], o);
            }
            #pragma unroll
            for (int u = 0; u < U; u++) {
                pacc.x += p[u] * v[u].x; pacc.y += p[u] * v[u].y;
                pacc.z += p[u] * v[u].z; pacc.w += p[u] * v[u].w;
            }
            r += U * NWARP;
        }
        for (; r < cend; r += NWARP) {
            float4 v = cache[(r - start) * 32 + lane];
            float p = v.x * c.x + v.y * c.y + v.z * c.z + v.w * c.w;
            #pragma unroll
            for (int o = 16; o; o >>= 1)
                p += __shfl_xor_sync(0xffffffffu, p, o);
            pacc.x += p * v.x; pacc.y += p * v.y; pacc.z += p * v.z; pacc.w += p * v.w;
        }
    }

    red[wid][lane] = pacc;
    __syncthreads();

    if (wid == 0) {
        float4 s = red[0][lane];
        #pragma unroll
        for (int w = 1; w < NWARP; w++) {
            float4 t = red[w][lane];
            s.x += t.x; s.y += t.y; s.z += t.z; s.w += t.w;
        }
        s.x *= inv_n; s.y *= inv_n; s.z *= inv_n; s.w *= inv_n;
        ((float4*)g_pooled)[(size_t)seg * 32 + lane] = s;
    }
}

// ---------------------------------------------------------------------------
// Kernel 3: out = pooled @ W^T + b    ([B,128] x [128,128])
// ---------------------------------------------------------------------------
__global__ __launch_bounds__(256)
void gemm_kernel(const float* __restrict__ W, const float* __restrict__ bias,
                 float* __restrict__ out, int B) {
    extern __shared__ float sm[];
    float* Wt = sm;                 // [128][132]
    float* ps = sm + 128 * 132;     // [GS][128]

    const int t  = threadIdx.x;
    const int s0 = blockIdx.x * GS;

    for (int idx = t; idx < D * D; idx += 256) {
        int o = idx >> 7, k = idx & 127;
        Wt[k * 132 + o] = W[idx];
    }
    {
        float4* ps4 = (float4*)ps;
        const float4* gp4 = (const float4*)(g_pooled + (size_t)s0 * D);
        int nvec = GS * D / 4;
        for (int idx = t; idx < nvec; idx += 256) {
            int row = s0 + (idx >> 5);
            ps4[idx] = (row < B) ? gp4[idx] : make_float4(0.f, 0.f, 0.f, 0.f);
        }
    }
    __syncthreads();

    const int o4 = (t & 31) * 4;
    const int sb = (t >> 5) * 4;

    float acc[4][4];
    #pragma unroll
    for (int j = 0; j < 4; j++)
        #pragma unroll
        for (int i = 0; i < 4; i++) acc[j][i] = 0.f;

    #pragma unroll 4
    for (int k = 0; k < D; k++) {
        float4 w4 = *(const float4*)&Wt[k * 132 + o4];
        #pragma unroll
        for (int j = 0; j < 4; j++) {
            float pv = ps[(sb + j) * D + k];
            acc[j][0] += pv * w4.x;
            acc[j][1] += pv * w4.y;
            acc[j][2] += pv * w4.z;
            acc[j][3] += pv * w4.w;
        }
    }

    float4 bb = *(const float4*)&bias[o4];
    #pragma unroll
    for (int j = 0; j < 4; j++) {
        int s = s0 + sb + j;
        if (s < B) {
            float4 r = make_float4(acc[j][0] + bb.x, acc[j][1] + bb.y,
                                   acc[j][2] + bb.z, acc[j][3] + bb.w);
            *(float4*)&out[(size_t)s * D + o4] = r;
        }
    }
}

// ---------------------------------------------------------------------------
extern "C" void kernel_launch(void* const* d_in, const int* in_sizes, int n_in,
                              void* d_out, int out_size) {
    const float* x     = (const float*)d_in[0];
    const int*   batch = (const int*)d_in[1];
    const float* W     = (const float*)d_in[2];
    const float* bias  = (const float*)d_in[3];
    (void)n_in;

    const int N = in_sizes[1];
    const int B = out_size / D;

    const size_t pool_smem = (size_t)CACHE_ROWS * 32 * sizeof(float4);   // 32 KB
    const size_t gemm_smem = (size_t)(128 * 132 + GS * D) * sizeof(float);

    cudaFuncSetAttribute(pool_kernel, cudaFuncAttributeMaxDynamicSharedMemorySize,
                         (int)pool_smem);
    cudaFuncSetAttribute(gemm_kernel, cudaFuncAttributeMaxDynamicSharedMemorySize,
                         (int)gemm_smem);

    int nvec4 = (N + 3) / 4;
    seg_scan_kernel<<<(nvec4 + 255) / 256, 256>>>(batch, N, B);
    pool_kernel<<<B, TPB, pool_smem>>>(x);
    gemm_kernel<<<(B + GS - 1) / GS, 256, gemm_smem>>>(W, bias, (float*)d_out, B);
}